// round 1
// baseline (speedup 1.0000x reference)
#include <cuda_runtime.h>
#include <cuda_bf16.h>

#define N_    4096
#define FIN_  500
#define H_    64
#define C_    7
#define E_    65536
#define B_    1024
#define A_    20
#define NW_   128          // bitset words per row (4096 bits)
#define CH_   (C_*H_)      // 448

// ---------------- scratch (device globals; no allocation allowed) ----------
__device__ float    g_embed[N_*H_];        // 1 MB
__device__ unsigned g_adj  [N_*NW_];       // 2 MB
__device__ unsigned g_hop2 [N_*NW_];       // 2 MB
__device__ int      g_cls  [N_];
__device__ float    g_anchor[C_*H_];
__device__ float    g_anchor_n2[C_];
__device__ float    g_thresh;
__device__ float    g_red[3*B_*CH_];       // 5.5 MB: ego|pos|neg reductions

// ---------------- 1) exact top-k threshold via 4-pass radix select ---------
__global__ void k_thresh(const float* __restrict__ w, int k) {
    __shared__ int hist[256];
    __shared__ unsigned s_prefix;
    __shared__ int s_k;
    int tid = threadIdx.x;
    if (tid == 0) { s_prefix = 0u; s_k = k; }
    __syncthreads();
    for (int p = 0; p < 4; p++) {
        if (tid < 256) hist[tid] = 0;
        __syncthreads();
        unsigned hm = (p == 0) ? 0u : (0xFFFFFFFFu << (32 - 8*p));
        int sh = 24 - 8*p;
        unsigned pref = s_prefix;
        for (int i = tid; i < E_; i += blockDim.x) {
            unsigned key = __float_as_uint(w[i]);
            if ((key & hm) == (pref & hm))
                atomicAdd(&hist[(key >> sh) & 0xFF], 1);
        }
        __syncthreads();
        if (tid == 0) {
            int cum = 0, kk = s_k;
            for (int b = 255; b >= 0; b--) {
                cum += hist[b];
                if (cum >= kk) {
                    s_prefix = pref | ((unsigned)b << sh);
                    s_k = kk - (cum - hist[b]);
                    break;
                }
            }
        }
        __syncthreads();
    }
    if (tid == 0) g_thresh = __uint_as_float(s_prefix);
}

// ---------------- 2) encoder: embed = relu(x @ W_enc + b_enc) --------------
// block = 256 threads, computes 32 rows x 64 cols; K tiled by 25 (500 = 20*25)
__global__ void k_encoder(const float* __restrict__ x,
                          const float* __restrict__ Wenc,
                          const float* __restrict__ benc) {
    const int KB = 25;
    __shared__ float xs[32][KB];
    __shared__ float ws[KB][64];
    int tid = threadIdx.x;
    int h  = tid & 63;
    int rg = tid >> 6;              // 0..3
    int r0 = blockIdx.x * 32;
    float acc[8];
#pragma unroll
    for (int i = 0; i < 8; i++) acc[i] = 0.f;
    for (int k0 = 0; k0 < FIN_; k0 += KB) {
        for (int i = tid; i < 32*KB; i += 256) {
            int r = i / KB, kk = i % KB;
            xs[r][kk] = x[(r0 + r)*FIN_ + k0 + kk];
        }
        for (int i = tid; i < KB*64; i += 256) {
            int kk = i / 64, hh = i % 64;
            ws[kk][hh] = Wenc[(k0 + kk)*64 + hh];
        }
        __syncthreads();
#pragma unroll
        for (int kk = 0; kk < KB; kk++) {
            float wv = ws[kk][h];
#pragma unroll
            for (int rr = 0; rr < 8; rr++)
                acc[rr] += xs[rg + rr*4][kk] * wv;
        }
        __syncthreads();
    }
    float bv = benc[h];
#pragma unroll
    for (int rr = 0; rr < 8; rr++) {
        int r = r0 + rg + rr*4;
        float v = acc[rr] + bv;
        g_embed[r*64 + h] = v > 0.f ? v : 0.f;
    }
}

// ---------------- 3) adjacency bitset ---------------------------------------
__global__ void k_clear() {
    int i = blockIdx.x * blockDim.x + threadIdx.x;
    if (i < N_*NW_) g_adj[i] = 0u;
}

__global__ void k_adj(const int* __restrict__ ei, const float* __restrict__ ew) {
    int i = blockIdx.x * blockDim.x + threadIdx.x;
    float th = g_thresh;
    if (i < E_) {
        if (ew[i] >= th) {
            int s = ei[i], d = ei[E_ + i];
            atomicOr(&g_adj[s*NW_ + (d >> 5)], 1u << (d & 31));
        }
    } else if (i < E_ + N_) {
        int n = i - E_;
        atomicOr(&g_adj[n*NW_ + (n >> 5)], 1u << (n & 31));   // diag
    }
}

// ---------------- 4) class anchors + norms ----------------------------------
__global__ void k_anchor(const int* __restrict__ aidx) {
    int c = blockIdx.x;
    int h = threadIdx.x;
    float s = 0.f;
    for (int a = 0; a < A_; a++) {
        int n = aidx[c*A_ + a];
        s += g_embed[n*64 + h];
    }
    s *= (1.f / A_);
    g_anchor[c*64 + h] = s;
    __shared__ float red[64];
    red[h] = s * s;
    __syncthreads();
    for (int o = 32; o > 0; o >>= 1) {
        if (h < o) red[h] += red[h + o];
        __syncthreads();
    }
    if (h == 0) g_anchor_n2[c] = red[0];
}

// ---------------- 5) per-node class assignment + x_out log_softmax ----------
__global__ void k_cls(const float* __restrict__ Wpred,
                      const float* __restrict__ bpred,
                      float* __restrict__ out) {
    int n = blockIdx.x * blockDim.x + threadIdx.x;
    if (n >= N_) return;
    float e[64];
    const float4* ep = (const float4*)(g_embed + n*64);
#pragma unroll
    for (int i = 0; i < 16; i++) {
        float4 v = ep[i];
        e[4*i] = v.x; e[4*i+1] = v.y; e[4*i+2] = v.z; e[4*i+3] = v.w;
    }
    float en2 = 0.f;
#pragma unroll
    for (int h = 0; h < 64; h++) en2 += e[h]*e[h];
    int best = 0; float bd = 3.4e38f;
    for (int c = 0; c < C_; c++) {
        float dot = 0.f;
#pragma unroll
        for (int h = 0; h < 64; h++) dot += e[h] * g_anchor[c*64 + h];
        float d2 = en2 - 2.f*dot + g_anchor_n2[c];
        if (d2 < bd) { bd = d2; best = c; }
    }
    g_cls[n] = best;
    float xo[C_];
    for (int c = 0; c < C_; c++) {
        float s = bpred[c];
#pragma unroll
        for (int h = 0; h < 64; h++) s += e[h] * Wpred[h*C_ + c];
        xo[c] = s;
    }
    float m = xo[0];
    for (int c = 1; c < C_; c++) m = fmaxf(m, xo[c]);
    float se = 0.f;
    for (int c = 0; c < C_; c++) se += expf(xo[c] - m);
    float ls = logf(se);
    for (int c = 0; c < C_; c++) out[2*B_ + n*C_ + c] = xo[c] - m - ls;
}

// ---------------- 6) 2-hop reachability: row-wise OR of neighbor bitsets ----
__global__ void k_hop2() {
    int i = blockIdx.x;
    int t = threadIdx.x;           // word-column 0..127
    __shared__ unsigned row[NW_];
    row[t] = g_adj[i*NW_ + t];
    __syncthreads();
    unsigned acc = row[t];         // adj row itself (includes diag)
    for (int w = 0; w < NW_; w++) {
        unsigned bits = row[w];
        while (bits) {
            int b = __ffs(bits) - 1;
            bits &= bits - 1;
            int j = w*32 + b;
            acc |= g_adj[j*NW_ + t];
        }
    }
    g_hop2[i*NW_ + t] = acc;
}

// ---------------- 7) sparse class-mean per query -----------------------------
__global__ void k_cmean(const int* __restrict__ ego,
                        const int* __restrict__ pos,
                        const int* __restrict__ neg) {
    int q = blockIdx.x;
    int v;
    if (q < B_)          v = ego[q];
    else if (q < 2*B_)   v = pos[q - B_];
    else                 v = neg[q - 2*B_];

    __shared__ float sums[CH_];
    __shared__ int   cnt[C_];
    __shared__ int   list[4096];
    __shared__ int   nlist;
    int tid = threadIdx.x;
    for (int i = tid; i < CH_; i += blockDim.x) sums[i] = 0.f;
    if (tid < C_) cnt[tid] = 0;
    if (tid == 0) nlist = 0;
    __syncthreads();

    for (int w = tid; w < NW_; w += blockDim.x) {
        unsigned bits = g_hop2[v*NW_ + w];
        while (bits) {
            int b = __ffs(bits) - 1;
            bits &= bits - 1;
            int p = atomicAdd(&nlist, 1);
            list[p] = w*32 + b;
        }
    }
    __syncthreads();
    int M = nlist;
    int lane = tid & 31, warp = tid >> 5;
    for (int li = warp; li < M; li += (int)(blockDim.x >> 5)) {
        int n = list[li];
        int c = g_cls[n];
        atomicAdd(&sums[c*64 + lane],      g_embed[n*64 + lane]);
        atomicAdd(&sums[c*64 + lane + 32], g_embed[n*64 + lane + 32]);
        if (lane == 0) atomicAdd(&cnt[c], 1);
    }
    __syncthreads();
    for (int i = tid; i < CH_; i += blockDim.x) {
        int c = i >> 6;
        float cc = (float)(cnt[c] > 0 ? cnt[c] : 1);
        g_red[q*CH_ + i] = sums[i] / cc;
    }
}

// ---------------- 8) decoder MLP on (e-p)^2 and (e-n)^2 ----------------------
__global__ void k_dec(const float* __restrict__ W1, const float* __restrict__ b1,
                      const float* __restrict__ W2, const float* __restrict__ b2,
                      float* __restrict__ out) {
    int b = blockIdx.x;
    __shared__ float op[CH_], on[CH_];
    __shared__ float part[4][32];
    int tid = threadIdx.x;
    const float* er = g_red + (size_t)b*CH_;
    const float* pr = g_red + (size_t)(B_ + b)*CH_;
    const float* nr = g_red + (size_t)(2*B_ + b)*CH_;
    for (int i = tid; i < CH_; i += 128) {
        float e = er[i];
        float dp = e - pr[i]; op[i] = dp*dp;
        float dn = e - nr[i]; on[i] = dn*dn;
    }
    __syncthreads();
    int lane = tid & 31, warp = tid >> 5;
    const float* o = (warp < 2) ? op : on;
    int i0 = (warp & 1) * 224;
    float h = 0.f;
    for (int i = i0; i < i0 + 224; i++)
        h += o[i] * W1[i*32 + lane];
    part[warp][lane] = h;
    __syncthreads();
    if (warp == 0) {
        float hv = part[0][lane] + part[1][lane] + b1[lane];
        hv = hv > 0.f ? hv : 0.f;
        float v = hv * W2[lane];
        for (int o2 = 16; o2 > 0; o2 >>= 1) v += __shfl_down_sync(0xffffffffu, v, o2);
        if (lane == 0) out[b] = v + b2[0];
    } else if (warp == 1) {
        float hv = part[2][lane] + part[3][lane] + b1[lane];
        hv = hv > 0.f ? hv : 0.f;
        float v = hv * W2[lane];
        for (int o2 = 16; o2 > 0; o2 >>= 1) v += __shfl_down_sync(0xffffffffu, v, o2);
        if (lane == 0) out[B_ + b] = v + b2[0];
    }
}

// ---------------- launch ------------------------------------------------------
extern "C" void kernel_launch(void* const* d_in, const int* in_sizes, int n_in,
                              void* d_out, int out_size) {
    const float* x    = (const float*)d_in[0];
    const int*   ei   = (const int*)  d_in[1];
    const int*   ego  = (const int*)  d_in[2];
    const int*   pos  = (const int*)  d_in[3];
    const int*   neg  = (const int*)  d_in[4];
    const float* ew   = (const float*)d_in[5];
    const int*   aidx = (const int*)  d_in[6];
    // d_in[7] may be the scalar `idx` (size 1) or already W_enc — probe size.
    int wb = (in_sizes[7] == FIN_*H_) ? 7 : 8;
    const float* Wenc  = (const float*)d_in[wb + 0];
    const float* benc  = (const float*)d_in[wb + 1];
    const float* Wpred = (const float*)d_in[wb + 2];
    const float* bpred = (const float*)d_in[wb + 3];
    const float* W1    = (const float*)d_in[wb + 4];
    const float* b1    = (const float*)d_in[wb + 5];
    const float* W2    = (const float*)d_in[wb + 6];
    const float* b2    = (const float*)d_in[wb + 7];
    float* out = (float*)d_out;

    k_thresh <<<1, 1024>>>(ew, E_/2);
    k_encoder<<<N_/32, 256>>>(x, Wenc, benc);
    k_clear  <<<(N_*NW_ + 255)/256, 256>>>();
    k_adj    <<<(E_ + N_ + 255)/256, 256>>>(ei, ew);
    k_anchor <<<C_, 64>>>(aidx);
    k_cls    <<<N_/128, 128>>>(Wpred, bpred, out);
    k_hop2   <<<N_, 128>>>();
    k_cmean  <<<3*B_, 256>>>(ego, pos, neg);
    k_dec    <<<B_, 128>>>(W1, b1, W2, b2, out);
}